// round 13
// baseline (speedup 1.0000x reference)
#include <cuda_runtime.h>
#include <cuda_fp16.h>
#include <math.h>
#include <stdint.h>

#define BB 1024
#define DD 512
#define KK 255
#define LL 256
#define CC 80
#define NGRP 16

#define WCH 11520      // W chunk: 80 rows x 144B (fp16)
#define XCH 18432      // X chunk: 128 rows x 144B (fp16)
#define NECH 9216      // ne chunk: 64 rows x 144B (fp16)

// ---- smem layout for k_main (bytes) ----
#define SM_X   0                     // 8 chunks x 18432 = 147456 (X resident)
#define SM_W   147456                // 4 bufs x 11520 = 46080
#define SM_PS  193536                // 128*17*4 = 8704
#define SM_BS  202240                // 16*80*4 = 5120
#define SM_MB  207360                // mbarriers (128B)
#define SMEM_MAIN 207488

// ---- smem layout for k_nsim (z=4) ----
#define NS_X   0                     // 2 kl x (xh 18432 + xl 18432) = 73728
#define NS_NE  73728                 // 2 kl x (neh 9216 + nel 9216) = 36864
#define NS_MB  110592
#define SMEM_NS 110720

// ---------------- device scratch ----------------
__device__ float g_probs[BB * LL];
__device__ float g_partial[NGRP * BB * CC];
__device__ float g_zp[4 * BB * 256];                            // nodesim k-split partials
__device__ __align__(16) uint8_t g_wb[(size_t)LL * 8 * WCH];    // [leaf][ks][80x144B] fp16
__device__ __align__(16) uint8_t g_xb[(size_t)8 * 8 * XCH];     // [rt][ks][128x144B] fp16 hi
__device__ __align__(16) uint8_t g_xl[(size_t)8 * 8 * XCH];     // fp16 lo residual
__device__ __align__(16) uint8_t g_neh[(size_t)4 * 8 * NECH];   // [cg][ks][64x144B] fp16 hi (row255=0)
__device__ __align__(16) uint8_t g_nel[(size_t)4 * 8 * NECH];   // fp16 lo residual

// ---------------- helpers ----------------
__device__ __forceinline__ uint32_t s2u(const void* p) {
    uint32_t a;
    asm("{ .reg .u64 t; cvta.to.shared.u64 t, %1; cvt.u32.u64 %0, t; }" : "=r"(a) : "l"(p));
    return a;
}
#define MBINIT(m, c)  asm volatile("mbarrier.init.shared.b64 [%0], %1;" :: "r"(m), "r"(c) : "memory")
#define MBEXPECT(m, b) asm volatile("mbarrier.arrive.expect_tx.shared.b64 _, [%0], %1;" :: "r"(m), "r"(b) : "memory")
#define MBARRIVE(m)   asm volatile("mbarrier.arrive.shared.b64 _, [%0];" :: "r"(m) : "memory")
__device__ __forceinline__ void mbwait(uint32_t m, uint32_t ph) {
    asm volatile(
        "{\n .reg .pred P;\n"
        "LW_%=:\n mbarrier.try_wait.parity.acquire.cta.shared::cta.b64 P, [%0], %1, 0x989680;\n"
        " @P bra LD_%=;\n bra LW_%=;\nLD_%=:\n}"
        :: "r"(m), "r"(ph) : "memory");
}
#define BULK(dst, src, sz, mb) \
    asm volatile("cp.async.bulk.shared::cta.global.mbarrier::complete_tx::bytes [%0], [%1], %2, [%3];" \
                 :: "r"(dst), "l"(src), "r"(sz), "r"(mb) : "memory")

__device__ __forceinline__ void ldsm4(uint32_t* r, uint32_t a) {
    asm volatile("ldmatrix.sync.aligned.m8n8.x4.shared.b16 {%0,%1,%2,%3}, [%4];"
        : "=r"(r[0]), "=r"(r[1]), "=r"(r[2]), "=r"(r[3]) : "r"(a));
}
__device__ __forceinline__ void ldsm2(uint32_t* r, uint32_t a) {
    asm volatile("ldmatrix.sync.aligned.m8n8.x2.shared.b16 {%0,%1}, [%2];"
        : "=r"(r[0]), "=r"(r[1]) : "r"(a));
}
__device__ __forceinline__ void mma_f16(float* c, const uint32_t* a, const uint32_t* b) {
    asm volatile(
        "mma.sync.aligned.m16n8k16.row.col.f32.f16.f16.f32 "
        "{%0,%1,%2,%3}, {%4,%5,%6,%7}, {%8,%9}, {%0,%1,%2,%3};"
        : "+f"(c[0]), "+f"(c[1]), "+f"(c[2]), "+f"(c[3])
        : "r"(a[0]), "r"(a[1]), "r"(a[2]), "r"(a[3]), "r"(b[0]), "r"(b[1]));
}

// ---------------- K1: normalize node embeddings -> fp16 hi/lo MMA layout ----------------
__global__ void k_norm(const float* __restrict__ ne) {
    int k = blockIdx.x;              // 0..254
    int t = threadIdx.x;             // 128
    const float* row = ne + (size_t)k * DD;
    float4 v = *(const float4*)(row + t * 4);
    float s = v.x * v.x + v.y * v.y + v.z * v.z + v.w * v.w;
    __shared__ float red[4];
    #pragma unroll
    for (int o = 16; o > 0; o >>= 1) s += __shfl_xor_sync(0xffffffffu, s, o);
    if ((t & 31) == 0) red[t >> 5] = s;
    __syncthreads();
    float inv = 1.0f / sqrtf(red[0] + red[1] + red[2] + red[3]);
    float vv[4] = {v.x * inv, v.y * inv, v.z * inv, v.w * inv};
    unsigned short hb[4], lb[4];
    #pragma unroll
    for (int i = 0; i < 4; ++i) {
        __half h = __float2half_rn(vv[i]);
        hb[i] = __half_as_ushort(h);
        lb[i] = __half_as_ushort(__float2half_rn(vv[i] - __half2float(h)));
    }
    int d0 = t * 4, ks = d0 >> 6, k8 = d0 & 63;
    int cg = k >> 6, r = k & 63;
    size_t off = (size_t)(cg * 8 + ks) * NECH + r * 144 + k8 * 2;
    *(uint2*)(g_neh + off) = make_uint2(((uint32_t)hb[1] << 16) | hb[0], ((uint32_t)hb[3] << 16) | hb[2]);
    *(uint2*)(g_nel + off) = make_uint2(((uint32_t)lb[1] << 16) | lb[0], ((uint32_t)lb[3] << 16) | lb[2]);
}

// ---------------- K2: node_sim logits via HMMA 3-term, k-split=4 ----------------
// grid (8 rt, 4 cg, 4 z), 256 threads = 8 warps (4M x 2N); warp tile 32x32.
__global__ void __launch_bounds__(256, 1) k_nsim() {
    extern __shared__ char smem[];
    const uint32_t sb = s2u(smem);
    const int tid = threadIdx.x;
    const int rt = blockIdx.x, cg = blockIdx.y, z = blockIdx.z;
    const int wid = tid >> 5, lane = tid & 31;
    const int wm = wid >> 1, wn = wid & 1;
    const int lr = lane >> 2, lc = lane & 3;

    const uint32_t FULL = sb + NS_MB;
    if (tid == 0) MBINIT(FULL, 1);
    __syncthreads();

    if (tid == 0) {
        MBEXPECT(FULL, 73728 + 36864);
        #pragma unroll
        for (int kl = 0; kl < 2; ++kl) {
            size_t xs = (size_t)(rt * 8 + z * 2 + kl) * XCH;
            BULK(sb + NS_X + kl * 36864, g_xb + xs, XCH, FULL);
            BULK(sb + NS_X + kl * 36864 + XCH, g_xl + xs, XCH, FULL);
            size_t ns_ = (size_t)(cg * 8 + z * 2 + kl) * NECH;
            BULK(sb + NS_NE + kl * 18432, g_neh + ns_, NECH, FULL);
            BULK(sb + NS_NE + kl * 18432 + NECH, g_nel + ns_, NECH, FULL);
        }
    }

    const uint32_t aoff0 = (uint32_t)(wm * 32 + ((lane >> 3) & 1) * 8 + (lane & 7)) * 144
                           + ((lane >> 4) & 1) * 16;
    const uint32_t aoff1 = aoff0 + 16 * 144;
    const uint32_t boff0 = (uint32_t)(wn * 32 + ((lane >> 4) & 1) * 8 + (lane & 7)) * 144
                           + ((lane >> 3) & 1) * 16;
    const uint32_t boff1 = boff0 + 16 * 144;

    float acc[2][4][4] = {};
    mbwait(FULL, 0);

    #pragma unroll
    for (int kl = 0; kl < 2; ++kl) {
        const uint32_t xh = sb + NS_X + kl * 36864;
        const uint32_t xl = xh + XCH;
        const uint32_t nh = sb + NS_NE + kl * 18432;
        const uint32_t nl = nh + NECH;
        #pragma unroll
        for (int kc = 0; kc < 4; ++kc) {
            const int ko = kc * 32;
            uint32_t ah[2][4], al[2][4], bh[4][2], bl[4][2];
            ldsm4(ah[0], xh + aoff0 + ko);
            ldsm4(ah[1], xh + aoff1 + ko);
            ldsm4(al[0], xl + aoff0 + ko);
            ldsm4(al[1], xl + aoff1 + ko);
            ldsm4(&bh[0][0], nh + boff0 + ko);
            ldsm4(&bh[2][0], nh + boff1 + ko);
            ldsm4(&bl[0][0], nl + boff0 + ko);
            ldsm4(&bl[2][0], nl + boff1 + ko);
            #pragma unroll
            for (int mt = 0; mt < 2; ++mt)
                #pragma unroll
                for (int nt = 0; nt < 4; ++nt) {
                    mma_f16(acc[mt][nt], ah[mt], bh[nt]);
                    mma_f16(acc[mt][nt], al[mt], bh[nt]);
                    mma_f16(acc[mt][nt], ah[mt], bl[nt]);
                }
        }
    }

    float* zp = g_zp + (size_t)z * BB * 256;
    #pragma unroll
    for (int mt = 0; mt < 2; ++mt) {
        int r0 = rt * 128 + wm * 32 + mt * 16 + lr;
        #pragma unroll
        for (int nt = 0; nt < 4; ++nt) {
            int c0 = cg * 64 + wn * 32 + nt * 8 + lc * 2;
            *(float2*)(zp + (size_t)r0 * 256 + c0) = make_float2(acc[mt][nt][0], acc[mt][nt][1]);
            *(float2*)(zp + (size_t)(r0 + 8) * 256 + c0) = make_float2(acc[mt][nt][2], acc[mt][nt][3]);
        }
    }
}

// ---------------- K3: combine partials, sigmoid, leaf probabilities ----------------
__global__ void k_probs(float* __restrict__ out_ns) {
    int b = blockIdx.x;
    int t = threadIdx.x;
    __shared__ float s[KK];
    if (t < KK) {
        size_t zrow = (size_t)b * 256 + t;
        float zv = g_zp[zrow] + g_zp[(size_t)BB * 256 + zrow]
                 + g_zp[(size_t)2 * BB * 256 + zrow] + g_zp[(size_t)3 * BB * 256 + zrow];
        float sig = 1.0f / (1.0f + expf(-zv));
        s[t] = sig;
        out_ns[(size_t)b * KK + t] = sig;
    }
    __syncthreads();
    float p = 1.0f; int node = 0;
    #pragma unroll
    for (int d = 0; d < 8; ++d) {
        int bit = (t >> (7 - d)) & 1;
        float v = s[node];
        p *= bit ? (1.0f - v) : v;
        node = 2 * node + 1 + bit;
    }
    g_probs[(size_t)b * LL + t] = p;
}

// ---------------- conversion kernels ----------------
__global__ void k_convW(const float* __restrict__ W) {
    int t = blockIdx.x * 256 + threadIdx.x;      // 20480*64
    int row = t >> 6;
    int kg = t & 63;
    int leaf = row / 80, n = row - leaf * 80;
    int ks = kg >> 3, k8 = kg & 7;
    float4 a = *(const float4*)(W + (size_t)row * 512 + kg * 8);
    float4 b = *(const float4*)(W + (size_t)row * 512 + kg * 8 + 4);
    float v[8] = {a.x, a.y, a.z, a.w, b.x, b.y, b.z, b.w};
    unsigned short hb[8];
    #pragma unroll
    for (int i = 0; i < 8; ++i) hb[i] = __half_as_ushort(__float2half_rn(v[i]));
    uint4 HI = make_uint4(((uint32_t)hb[1] << 16) | hb[0], ((uint32_t)hb[3] << 16) | hb[2],
                          ((uint32_t)hb[5] << 16) | hb[4], ((uint32_t)hb[7] << 16) | hb[6]);
    *(uint4*)(g_wb + (size_t)(leaf * 8 + ks) * WCH + n * 144 + k8 * 16) = HI;
}
__global__ void k_convX(const float* __restrict__ x) {
    int t = blockIdx.x * 256 + threadIdx.x;      // 1024*64
    int row = t >> 6;
    int kg = t & 63;
    int rt = row >> 7, r = row & 127;
    int ks = kg >> 3, k8 = kg & 7;
    float4 a = *(const float4*)(x + (size_t)row * 512 + kg * 8);
    float4 b = *(const float4*)(x + (size_t)row * 512 + kg * 8 + 4);
    float v[8] = {a.x, a.y, a.z, a.w, b.x, b.y, b.z, b.w};
    unsigned short hb[8], lb[8];
    #pragma unroll
    for (int i = 0; i < 8; ++i) {
        __half h = __float2half_rn(v[i]);
        hb[i] = __half_as_ushort(h);
        lb[i] = __half_as_ushort(__float2half_rn(v[i] - __half2float(h)));
    }
    size_t off = (size_t)(rt * 8 + ks) * XCH + r * 144 + k8 * 16;
    *(uint4*)(g_xb + off) = make_uint4(((uint32_t)hb[1] << 16) | hb[0], ((uint32_t)hb[3] << 16) | hb[2],
                                       ((uint32_t)hb[5] << 16) | hb[4], ((uint32_t)hb[7] << 16) | hb[6]);
    *(uint4*)(g_xl + off) = make_uint4(((uint32_t)lb[1] << 16) | lb[0], ((uint32_t)lb[3] << 16) | lb[2],
                                       ((uint32_t)lb[5] << 16) | lb[4], ((uint32_t)lb[7] << 16) | lb[6]);
}

// ---------------- K5: main HMMA kernel (leaf-outer, X resident) ----------------
// grid (8 rowtiles, 16 leaf-groups), 256 threads = 8 warps (4 M x 2 N).
__global__ void __launch_bounds__(256, 1) k_main(const float* __restrict__ bias) {
    extern __shared__ char smem[];
    const uint32_t sb = s2u(smem);
    const int tid = threadIdx.x;
    const int rt = blockIdx.x, grp = blockIdx.y;
    const int wid = tid >> 5, lane = tid & 31;
    const int wm = wid >> 1, wn = wid & 1;
    const int lr = lane >> 2, lc = lane & 3;

    const uint32_t MB = sb + SM_MB;
    #define WFULL(b)  (MB + (b) * 8)
    #define WEMPTY(b) (MB + 32 + (b) * 8)
    #define XFULL     (MB + 64)

    if (tid == 0) {
        for (int b = 0; b < 4; ++b) { MBINIT(WFULL(b), 1); MBINIT(WEMPTY(b), 8); }
        MBINIT(XFULL, 1);
    }
    float* psm = (float*)(smem + SM_PS);
    float* bsm = (float*)(smem + SM_BS);
    for (int j = tid; j < 128 * 16; j += 256) {
        int r = j >> 4, l = j & 15;
        psm[r * 17 + l] = g_probs[(size_t)(rt * 128 + r) * LL + grp * 16 + l];
    }
    for (int j = tid; j < 16 * CC; j += 256) bsm[j] = bias[grp * 16 * CC + j];
    __syncthreads();

    if (tid == 0) {
        MBEXPECT(XFULL, 8 * XCH);
        #pragma unroll
        for (int j = 0; j < 8; ++j)
            BULK(sb + SM_X + j * XCH, g_xb + (size_t)(rt * 8 + j) * XCH, XCH, XFULL);
        #pragma unroll
        for (int s = 0; s < 3; ++s) {
            MBEXPECT(WFULL(s), WCH);
            BULK(sb + SM_W + s * WCH,
                 g_wb + (size_t)(grp * 16 * 8 + s) * WCH, WCH, WFULL(s));
        }
    }

    const uint32_t aoff0 = (uint32_t)(wm * 32 + ((lane >> 3) & 1) * 8 + (lane & 7)) * 144
                           + ((lane >> 4) & 1) * 16;
    const uint32_t aoff1 = aoff0 + 16 * 144;
    const uint32_t boff0 = (uint32_t)(wn * 40 + ((lane >> 4) & 1) * 8 + (lane & 7)) * 144
                           + ((lane >> 3) & 1) * 16;
    const uint32_t boff1 = boff0 + 16 * 144;
    const int l16 = lane & 15;
    const uint32_t boff2 = (uint32_t)(wn * 40 + 32 + (l16 & 7)) * 144 + ((l16 >> 3) & 1) * 16;

    float per[2][5][4] = {};
    int cwf[4] = {0, 0, 0, 0}, pwe[4] = {0, 0, 0, 0};

    mbwait(XFULL, 0);

    for (int leaf = 0; leaf < 16; ++leaf) {
        float acc[2][5][4];
        #pragma unroll
        for (int nt = 0; nt < 5; ++nt) {
            int c0 = wn * 40 + nt * 8 + lc * 2;
            float b0 = bsm[leaf * CC + c0], b1 = bsm[leaf * CC + c0 + 1];
            #pragma unroll
            for (int mt = 0; mt < 2; ++mt) {
                acc[mt][nt][0] = b0; acc[mt][nt][1] = b1;
                acc[mt][nt][2] = b0; acc[mt][nt][3] = b1;
            }
        }

        for (int ks = 0; ks < 8; ++ks) {
            const int s = leaf * 8 + ks, b = s & 3;

            if (tid == 0) {
                int sn = s + 3;
                if (sn < 128) {
                    int bn = sn & 3;
                    if (sn >= 4) { mbwait(WEMPTY(bn), pwe[bn] & 1); pwe[bn]++; }
                    MBEXPECT(WFULL(bn), WCH);
                    BULK(sb + SM_W + bn * WCH,
                         g_wb + (size_t)(grp * 16 * 8 + sn) * WCH, WCH, WFULL(bn));
                }
            }

            mbwait(WFULL(b), cwf[b] & 1); cwf[b]++;
            const uint32_t xk = sb + SM_X + ks * XCH;
            const uint32_t wh = sb + SM_W + b * WCH;

            #pragma unroll
            for (int kc = 0; kc < 4; ++kc) {
                const int ko = kc * 32;
                uint32_t ah[2][4], bh[5][2];
                ldsm4(ah[0], xk + aoff0 + ko);
                ldsm4(ah[1], xk + aoff1 + ko);
                ldsm4(&bh[0][0], wh + boff0 + ko);
                ldsm4(&bh[2][0], wh + boff1 + ko);
                ldsm2(&bh[4][0], wh + boff2 + ko);
                #pragma unroll
                for (int mt = 0; mt < 2; ++mt)
                    #pragma unroll
                    for (int nt = 0; nt < 5; ++nt)
                        mma_f16(acc[mt][nt], ah[mt], bh[nt]);
            }

            if (lane == 0) MBARRIVE(WEMPTY(b));
        }

        #pragma unroll
        for (int mt = 0; mt < 2; ++mt) {
            float p0 = psm[(wm * 32 + mt * 16 + lr) * 17 + leaf];
            float p1 = psm[(wm * 32 + mt * 16 + 8 + lr) * 17 + leaf];
            #pragma unroll
            for (int nt = 0; nt < 5; ++nt) {
                per[mt][nt][0] = fmaf(p0, acc[mt][nt][0], per[mt][nt][0]);
                per[mt][nt][1] = fmaf(p0, acc[mt][nt][1], per[mt][nt][1]);
                per[mt][nt][2] = fmaf(p1, acc[mt][nt][2], per[mt][nt][2]);
                per[mt][nt][3] = fmaf(p1, acc[mt][nt][3], per[mt][nt][3]);
            }
        }
    }

    float* base = g_partial + (size_t)grp * BB * CC;
    #pragma unroll
    for (int mt = 0; mt < 2; ++mt) {
        int r0 = rt * 128 + wm * 32 + mt * 16 + lr;
        #pragma unroll
        for (int nt = 0; nt < 5; ++nt) {
            int c0 = wn * 40 + nt * 8 + lc * 2;
            *(float2*)(base + (size_t)r0 * CC + c0) = make_float2(per[mt][nt][0], per[mt][nt][1]);
            *(float2*)(base + (size_t)(r0 + 8) * CC + c0) = make_float2(per[mt][nt][2], per[mt][nt][3]);
        }
    }
}

// ---------------- K6: reduce partials ----------------
__global__ void k_reduce(float* __restrict__ out) {
    int idx = blockIdx.x * 256 + threadIdx.x;
    float s = 0.f;
    #pragma unroll
    for (int g = 0; g < NGRP; ++g)
        s += g_partial[(size_t)g * BB * CC + idx];
    out[idx] = s;
}

// ---------------- launch (R10-proven fork/join: 1 stream, 2 events per call) ----------------
extern "C" void kernel_launch(void* const* d_in, const int* in_sizes, int n_in,
                              void* d_out, int out_size) {
    const float* x    = (const float*)d_in[0];
    const float* ne   = (const float*)d_in[1];
    const float* W    = (const float*)d_in[2];
    const float* bias = (const float*)d_in[3];

    float* out1 = (float*)d_out;
    float* ns   = (float*)d_out + BB * CC;

    cudaFuncSetAttribute(k_main, cudaFuncAttributeMaxDynamicSharedMemorySize, SMEM_MAIN);
    cudaFuncSetAttribute(k_nsim, cudaFuncAttributeMaxDynamicSharedMemorySize, SMEM_NS);

    cudaStream_t s2;
    cudaEvent_t eFork, eJoin;
    cudaStreamCreateWithFlags(&s2, cudaStreamNonBlocking);
    cudaEventCreateWithFlags(&eFork, cudaEventDisableTiming);
    cudaEventCreateWithFlags(&eJoin, cudaEventDisableTiming);

    cudaEventRecord(eFork, 0);
    cudaStreamWaitEvent(s2, eFork, 0);

    // branch A (side stream): W conversion
    k_convW<<<5120, 256, 0, s2>>>(W);
    cudaEventRecord(eJoin, s2);

    // branch B (main stream): x conversion -> ne norm -> node-sim HMMA (z=4) -> probs
    k_convX<<<256, 256>>>(x);
    k_norm<<<KK, 128>>>(ne);
    dim3 gn(8, 4, 4);
    k_nsim<<<gn, 256, SMEM_NS>>>();
    k_probs<<<BB, 256>>>(ns);

    cudaStreamWaitEvent(0, eJoin, 0);
    dim3 g5(8, NGRP);
    k_main<<<g5, 256, SMEM_MAIN>>>(bias);
    k_reduce<<<(BB * CC) / 256, 256>>>(out1);

    // note: s2/eFork/eJoin intentionally not destroyed — destroying
    // capture-referenced handles mid-capture is UB; bounded leak (R10-proven clean).
}

// round 14
// speedup vs baseline: 1.0077x; 1.0077x over previous
#include <cuda_runtime.h>
#include <cuda_fp16.h>
#include <math.h>
#include <stdint.h>

#define BB 1024
#define DD 512
#define KK 255
#define LL 256
#define CC 80
#define NGRP 16

#define WCH 11520      // W chunk: 80 rows x 144B (fp16)
#define XCH 18432      // X chunk: 128 rows x 144B (fp16)
#define NECH 9216      // ne chunk: 64 rows x 144B (fp16)

// ---- smem layout for k_main (bytes) ----
#define SM_X   0                     // 8 chunks x 18432 = 147456 (X resident)
#define SM_W   147456                // 4 bufs x 11520 = 46080
#define SM_SG  (SM_W + 3 * WCH)      // sigmoid scratch INSIDE W slot 3 (dead until s=0 BULK)
#define SM_PS  193536                // 128*17*4 = 8704
#define SM_BS  202240                // 16*80*4 = 5120
#define SM_MB  207360                // mbarriers (128B)
#define SMEM_MAIN 207488

// ---- smem layout for k_nsim (z=4) ----
#define NS_X   0                     // 2 kl x (xh 18432 + xl 18432) = 73728
#define NS_NE  73728                 // 2 kl x (neh 9216 + nel 9216) = 36864
#define NS_MB  110592
#define SMEM_NS 110720

// ---------------- device scratch ----------------
__device__ float g_partial[NGRP * BB * CC];
__device__ float g_zp[4 * BB * 256];                            // nodesim k-split partials
__device__ __align__(16) uint8_t g_wb[(size_t)LL * 8 * WCH];    // [leaf][ks][80x144B] fp16
__device__ __align__(16) uint8_t g_xb[(size_t)8 * 8 * XCH];     // [rt][ks][128x144B] fp16 hi
__device__ __align__(16) uint8_t g_xl[(size_t)8 * 8 * XCH];     // fp16 lo residual
__device__ __align__(16) uint8_t g_neh[(size_t)4 * 8 * NECH];   // [cg][ks][64x144B] fp16 hi (row255=0)
__device__ __align__(16) uint8_t g_nel[(size_t)4 * 8 * NECH];   // fp16 lo residual

// ---------------- helpers ----------------
__device__ __forceinline__ uint32_t s2u(const void* p) {
    uint32_t a;
    asm("{ .reg .u64 t; cvta.to.shared.u64 t, %1; cvt.u32.u64 %0, t; }" : "=r"(a) : "l"(p));
    return a;
}
#define MBINIT(m, c)  asm volatile("mbarrier.init.shared.b64 [%0], %1;" :: "r"(m), "r"(c) : "memory")
#define MBEXPECT(m, b) asm volatile("mbarrier.arrive.expect_tx.shared.b64 _, [%0], %1;" :: "r"(m), "r"(b) : "memory")
#define MBARRIVE(m)   asm volatile("mbarrier.arrive.shared.b64 _, [%0];" :: "r"(m) : "memory")
__device__ __forceinline__ void mbwait(uint32_t m, uint32_t ph) {
    asm volatile(
        "{\n .reg .pred P;\n"
        "LW_%=:\n mbarrier.try_wait.parity.acquire.cta.shared::cta.b64 P, [%0], %1, 0x989680;\n"
        " @P bra LD_%=;\n bra LW_%=;\nLD_%=:\n}"
        :: "r"(m), "r"(ph) : "memory");
}
#define BULK(dst, src, sz, mb) \
    asm volatile("cp.async.bulk.shared::cta.global.mbarrier::complete_tx::bytes [%0], [%1], %2, [%3];" \
                 :: "r"(dst), "l"(src), "r"(sz), "r"(mb) : "memory")

__device__ __forceinline__ void ldsm4(uint32_t* r, uint32_t a) {
    asm volatile("ldmatrix.sync.aligned.m8n8.x4.shared.b16 {%0,%1,%2,%3}, [%4];"
        : "=r"(r[0]), "=r"(r[1]), "=r"(r[2]), "=r"(r[3]) : "r"(a));
}
__device__ __forceinline__ void ldsm2(uint32_t* r, uint32_t a) {
    asm volatile("ldmatrix.sync.aligned.m8n8.x2.shared.b16 {%0,%1}, [%2];"
        : "=r"(r[0]), "=r"(r[1]) : "r"(a));
}
__device__ __forceinline__ void mma_f16(float* c, const uint32_t* a, const uint32_t* b) {
    asm volatile(
        "mma.sync.aligned.m16n8k16.row.col.f32.f16.f16.f32 "
        "{%0,%1,%2,%3}, {%4,%5,%6,%7}, {%8,%9}, {%0,%1,%2,%3};"
        : "+f"(c[0]), "+f"(c[1]), "+f"(c[2]), "+f"(c[3])
        : "r"(a[0]), "r"(a[1]), "r"(a[2]), "r"(a[3]), "r"(b[0]), "r"(b[1]));
}

// ---------------- K1: normalize node embeddings -> fp16 hi/lo MMA layout ----------------
__global__ void k_norm(const float* __restrict__ ne) {
    int k = blockIdx.x;              // 0..254
    int t = threadIdx.x;             // 128
    const float* row = ne + (size_t)k * DD;
    float4 v = *(const float4*)(row + t * 4);
    float s = v.x * v.x + v.y * v.y + v.z * v.z + v.w * v.w;
    __shared__ float red[4];
    #pragma unroll
    for (int o = 16; o > 0; o >>= 1) s += __shfl_xor_sync(0xffffffffu, s, o);
    if ((t & 31) == 0) red[t >> 5] = s;
    __syncthreads();
    float inv = 1.0f / sqrtf(red[0] + red[1] + red[2] + red[3]);
    float vv[4] = {v.x * inv, v.y * inv, v.z * inv, v.w * inv};
    unsigned short hb[4], lb[4];
    #pragma unroll
    for (int i = 0; i < 4; ++i) {
        __half h = __float2half_rn(vv[i]);
        hb[i] = __half_as_ushort(h);
        lb[i] = __half_as_ushort(__float2half_rn(vv[i] - __half2float(h)));
    }
    int d0 = t * 4, ks = d0 >> 6, k8 = d0 & 63;
    int cg = k >> 6, r = k & 63;
    size_t off = (size_t)(cg * 8 + ks) * NECH + r * 144 + k8 * 2;
    *(uint2*)(g_neh + off) = make_uint2(((uint32_t)hb[1] << 16) | hb[0], ((uint32_t)hb[3] << 16) | hb[2]);
    *(uint2*)(g_nel + off) = make_uint2(((uint32_t)lb[1] << 16) | lb[0], ((uint32_t)lb[3] << 16) | lb[2]);
}

// ---------------- K2: node_sim logits via HMMA 3-term, k-split=4 ----------------
__global__ void __launch_bounds__(256, 1) k_nsim() {
    extern __shared__ char smem[];
    const uint32_t sb = s2u(smem);
    const int tid = threadIdx.x;
    const int rt = blockIdx.x, cg = blockIdx.y, z = blockIdx.z;
    const int wid = tid >> 5, lane = tid & 31;
    const int wm = wid >> 1, wn = wid & 1;
    const int lr = lane >> 2, lc = lane & 3;

    const uint32_t FULL = sb + NS_MB;
    if (tid == 0) MBINIT(FULL, 1);
    __syncthreads();

    if (tid == 0) {
        MBEXPECT(FULL, 73728 + 36864);
        #pragma unroll
        for (int kl = 0; kl < 2; ++kl) {
            size_t xs = (size_t)(rt * 8 + z * 2 + kl) * XCH;
            BULK(sb + NS_X + kl * 36864, g_xb + xs, XCH, FULL);
            BULK(sb + NS_X + kl * 36864 + XCH, g_xl + xs, XCH, FULL);
            size_t ns_ = (size_t)(cg * 8 + z * 2 + kl) * NECH;
            BULK(sb + NS_NE + kl * 18432, g_neh + ns_, NECH, FULL);
            BULK(sb + NS_NE + kl * 18432 + NECH, g_nel + ns_, NECH, FULL);
        }
    }

    const uint32_t aoff0 = (uint32_t)(wm * 32 + ((lane >> 3) & 1) * 8 + (lane & 7)) * 144
                           + ((lane >> 4) & 1) * 16;
    const uint32_t aoff1 = aoff0 + 16 * 144;
    const uint32_t boff0 = (uint32_t)(wn * 32 + ((lane >> 4) & 1) * 8 + (lane & 7)) * 144
                           + ((lane >> 3) & 1) * 16;
    const uint32_t boff1 = boff0 + 16 * 144;

    float acc[2][4][4] = {};
    mbwait(FULL, 0);

    #pragma unroll
    for (int kl = 0; kl < 2; ++kl) {
        const uint32_t xh = sb + NS_X + kl * 36864;
        const uint32_t xl = xh + XCH;
        const uint32_t nh = sb + NS_NE + kl * 18432;
        const uint32_t nl = nh + NECH;
        #pragma unroll
        for (int kc = 0; kc < 4; ++kc) {
            const int ko = kc * 32;
            uint32_t ah[2][4], al[2][4], bh[4][2], bl[4][2];
            ldsm4(ah[0], xh + aoff0 + ko);
            ldsm4(ah[1], xh + aoff1 + ko);
            ldsm4(al[0], xl + aoff0 + ko);
            ldsm4(al[1], xl + aoff1 + ko);
            ldsm4(&bh[0][0], nh + boff0 + ko);
            ldsm4(&bh[2][0], nh + boff1 + ko);
            ldsm4(&bl[0][0], nl + boff0 + ko);
            ldsm4(&bl[2][0], nl + boff1 + ko);
            #pragma unroll
            for (int mt = 0; mt < 2; ++mt)
                #pragma unroll
                for (int nt = 0; nt < 4; ++nt) {
                    mma_f16(acc[mt][nt], ah[mt], bh[nt]);
                    mma_f16(acc[mt][nt], al[mt], bh[nt]);
                    mma_f16(acc[mt][nt], ah[mt], bl[nt]);
                }
        }
    }

    float* zp = g_zp + (size_t)z * BB * 256;
    #pragma unroll
    for (int mt = 0; mt < 2; ++mt) {
        int r0 = rt * 128 + wm * 32 + mt * 16 + lr;
        #pragma unroll
        for (int nt = 0; nt < 4; ++nt) {
            int c0 = cg * 64 + wn * 32 + nt * 8 + lc * 2;
            *(float2*)(zp + (size_t)r0 * 256 + c0) = make_float2(acc[mt][nt][0], acc[mt][nt][1]);
            *(float2*)(zp + (size_t)(r0 + 8) * 256 + c0) = make_float2(acc[mt][nt][2], acc[mt][nt][3]);
        }
    }
}

// ---------------- K3: ns output (side stream, overlaps k_main) ----------------
__global__ void k_nsout(float* __restrict__ out_ns) {
    int b = blockIdx.x;
    int t = threadIdx.x;
    if (t < KK) {
        size_t zrow = (size_t)b * 256 + t;
        float zz = g_zp[zrow] + g_zp[(size_t)BB * 256 + zrow]
                 + g_zp[(size_t)2 * BB * 256 + zrow] + g_zp[(size_t)3 * BB * 256 + zrow];
        out_ns[(size_t)b * KK + t] = 1.0f / (1.0f + expf(-zz));
    }
}

// ---------------- conversion kernels ----------------
__global__ void k_convW(const float* __restrict__ W) {
    int t = blockIdx.x * 256 + threadIdx.x;      // 20480*64
    int row = t >> 6;
    int kg = t & 63;
    int leaf = row / 80, n = row - leaf * 80;
    int ks = kg >> 3, k8 = kg & 7;
    float4 a = *(const float4*)(W + (size_t)row * 512 + kg * 8);
    float4 b = *(const float4*)(W + (size_t)row * 512 + kg * 8 + 4);
    float v[8] = {a.x, a.y, a.z, a.w, b.x, b.y, b.z, b.w};
    unsigned short hb[8];
    #pragma unroll
    for (int i = 0; i < 8; ++i) hb[i] = __half_as_ushort(__float2half_rn(v[i]));
    uint4 HI = make_uint4(((uint32_t)hb[1] << 16) | hb[0], ((uint32_t)hb[3] << 16) | hb[2],
                          ((uint32_t)hb[5] << 16) | hb[4], ((uint32_t)hb[7] << 16) | hb[6]);
    *(uint4*)(g_wb + (size_t)(leaf * 8 + ks) * WCH + n * 144 + k8 * 16) = HI;
}
__global__ void k_convX(const float* __restrict__ x) {
    int t = blockIdx.x * 256 + threadIdx.x;      // 1024*64
    int row = t >> 6;
    int kg = t & 63;
    int rt = row >> 7, r = row & 127;
    int ks = kg >> 3, k8 = kg & 7;
    float4 a = *(const float4*)(x + (size_t)row * 512 + kg * 8);
    float4 b = *(const float4*)(x + (size_t)row * 512 + kg * 8 + 4);
    float v[8] = {a.x, a.y, a.z, a.w, b.x, b.y, b.z, b.w};
    unsigned short hb[8], lb[8];
    #pragma unroll
    for (int i = 0; i < 8; ++i) {
        __half h = __float2half_rn(v[i]);
        hb[i] = __half_as_ushort(h);
        lb[i] = __half_as_ushort(__float2half_rn(v[i] - __half2float(h)));
    }
    size_t off = (size_t)(rt * 8 + ks) * XCH + r * 144 + k8 * 16;
    *(uint4*)(g_xb + off) = make_uint4(((uint32_t)hb[1] << 16) | hb[0], ((uint32_t)hb[3] << 16) | hb[2],
                                       ((uint32_t)hb[5] << 16) | hb[4], ((uint32_t)hb[7] << 16) | hb[6]);
    *(uint4*)(g_xl + off) = make_uint4(((uint32_t)lb[1] << 16) | lb[0], ((uint32_t)lb[3] << 16) | lb[2],
                                       ((uint32_t)lb[5] << 16) | lb[4], ((uint32_t)lb[7] << 16) | lb[6]);
}

// ---------------- K5: main HMMA kernel (leaf-outer, X resident, fused probs) ----------------
__global__ void __launch_bounds__(256, 1) k_main(const float* __restrict__ bias) {
    extern __shared__ char smem[];
    const uint32_t sb = s2u(smem);
    const int tid = threadIdx.x;
    const int rt = blockIdx.x, grp = blockIdx.y;
    const int wid = tid >> 5, lane = tid & 31;
    const int wm = wid >> 1, wn = wid & 1;
    const int lr = lane >> 2, lc = lane & 3;

    const uint32_t MB = sb + SM_MB;
    #define WFULL(b)  (MB + (b) * 8)
    #define WEMPTY(b) (MB + 32 + (b) * 8)
    #define XFULL     (MB + 64)

    if (tid == 0) {
        for (int b = 0; b < 4; ++b) { MBINIT(WFULL(b), 1); MBINIT(WEMPTY(b), 8); }
        MBINIT(XFULL, 1);
    }
    __syncthreads();

    // issue bulk loads first (X + W slots 0..2 only) so prologue math overlaps them
    if (tid == 0) {
        MBEXPECT(XFULL, 8 * XCH);
        #pragma unroll
        for (int j = 0; j < 8; ++j)
            BULK(sb + SM_X + j * XCH, g_xb + (size_t)(rt * 8 + j) * XCH, XCH, XFULL);
        #pragma unroll
        for (int s = 0; s < 3; ++s) {
            MBEXPECT(WFULL(s), WCH);
            BULK(sb + SM_W + s * WCH,
                 g_wb + (size_t)(grp * 16 * 8 + s) * WCH, WCH, WFULL(s));
        }
    }

    float* psm = (float*)(smem + SM_PS);
    float* bsm = (float*)(smem + SM_BS);
    float* sgm = (float*)(smem + SM_SG);    // [128 rows][19 nodes], lives in W slot 3
    for (int j = tid; j < 16 * CC; j += 256) bsm[j] = bias[grp * 16 * CC + j];

    // phase 1: 256 threads compute sigmoids for (row, node) tasks
    {
        int nd[19];
        nd[0] = 0;
        nd[1] = 1 + (grp >> 3);
        nd[2] = 3 + (grp >> 2);
        nd[3] = 7 + (grp >> 1);
        nd[4] = 15 + grp;
        nd[5] = 31 + 2 * grp; nd[6] = nd[5] + 1;
        #pragma unroll
        for (int j = 0; j < 4; ++j) nd[7 + j] = 63 + 4 * grp + j;
        #pragma unroll
        for (int j = 0; j < 8; ++j) nd[11 + j] = 127 + 8 * grp + j;
        for (int task = tid; task < 128 * 19; task += 256) {
            int r = task / 19, t19 = task - r * 19;
            size_t zrow = (size_t)(rt * 128 + r) * 256 + nd[t19];
            float zz = g_zp[zrow] + g_zp[(size_t)BB * 256 + zrow]
                     + g_zp[(size_t)2 * BB * 256 + zrow] + g_zp[(size_t)3 * BB * 256 + zrow];
            sgm[r * 19 + t19] = 1.0f / (1.0f + expf(-zz));
        }
    }
    __syncthreads();

    // phase 2: 128 threads fold 16 leaf products (root->leaf order, matches k_probs)
    if (tid < 128) {
        const float* sg = sgm + tid * 19;
        float P4 = 1.0f;
        #pragma unroll
        for (int d = 0; d < 4; ++d) {
            int bit = (grp >> (3 - d)) & 1;
            P4 *= bit ? (1.0f - sg[d]) : sg[d];
        }
        #pragma unroll
        for (int i = 0; i < 16; ++i) {
            float p = P4;
            p *= ((i >> 3) & 1) ? (1.0f - sg[4]) : sg[4];
            float v5 = sg[5 + (i >> 3)];
            p *= ((i >> 2) & 1) ? (1.0f - v5) : v5;
            float v6 = sg[7 + (i >> 2)];
            p *= ((i >> 1) & 1) ? (1.0f - v6) : v6;
            float v7 = sg[11 + (i >> 1)];
            p *= (i & 1) ? (1.0f - v7) : v7;
            psm[tid * 17 + i] = p;
        }
    }
    __syncthreads();   // sgm (W slot 3) dead after this point; slot-3 BULK issued below at s=0

    const uint32_t aoff0 = (uint32_t)(wm * 32 + ((lane >> 3) & 1) * 8 + (lane & 7)) * 144
                           + ((lane >> 4) & 1) * 16;
    const uint32_t aoff1 = aoff0 + 16 * 144;
    const uint32_t boff0 = (uint32_t)(wn * 40 + ((lane >> 4) & 1) * 8 + (lane & 7)) * 144
                           + ((lane >> 3) & 1) * 16;
    const uint32_t boff1 = boff0 + 16 * 144;
    const int l16 = lane & 15;
    const uint32_t boff2 = (uint32_t)(wn * 40 + 32 + (l16 & 7)) * 144 + ((l16 >> 3) & 1) * 16;

    float per[2][5][4] = {};
    int cwf[4] = {0, 0, 0, 0}, pwe[4] = {0, 0, 0, 0};

    mbwait(XFULL, 0);

    for (int leaf = 0; leaf < 16; ++leaf) {
        float acc[2][5][4];
        #pragma unroll
        for (int nt = 0; nt < 5; ++nt) {
            int c0 = wn * 40 + nt * 8 + lc * 2;
            float b0 = bsm[leaf * CC + c0], b1 = bsm[leaf * CC + c0 + 1];
            #pragma unroll
            for (int mt = 0; mt < 2; ++mt) {
                acc[mt][nt][0] = b0; acc[mt][nt][1] = b1;
                acc[mt][nt][2] = b0; acc[mt][nt][3] = b1;
            }
        }

        for (int ks = 0; ks < 8; ++ks) {
            const int s = leaf * 8 + ks, b = s & 3;

            if (tid == 0) {
                int sn = s + 3;
                if (sn < 128) {
                    int bn = sn & 3;
                    if (sn >= 4) { mbwait(WEMPTY(bn), pwe[bn] & 1); pwe[bn]++; }
                    MBEXPECT(WFULL(bn), WCH);
                    BULK(sb + SM_W + bn * WCH,
                         g_wb + (size_t)(grp * 16 * 8 + sn) * WCH, WCH, WFULL(bn));
                }
            }

            mbwait(WFULL(b), cwf[b] & 1); cwf[b]++;
            const uint32_t xk = sb + SM_X + ks * XCH;
            const uint32_t wh = sb + SM_W + b * WCH;

            #pragma unroll
            for (int kc = 0; kc < 4; ++kc) {
                const int ko = kc * 32;
                uint32_t ah[2][4], bh[5][2];
                ldsm4(ah[0], xk + aoff0 + ko);
                ldsm4(ah[1], xk + aoff1 + ko);
                ldsm4(&bh[0][0], wh + boff0 + ko);
                ldsm4(&bh[2][0], wh + boff1 + ko);
                ldsm2(&bh[4][0], wh + boff2 + ko);
                #pragma unroll
                for (int mt = 0; mt < 2; ++mt)
                    #pragma unroll
                    for (int nt = 0; nt < 5; ++nt)
                        mma_f16(acc[mt][nt], ah[mt], bh[nt]);
            }

            if (lane == 0) MBARRIVE(WEMPTY(b));
        }

        #pragma unroll
        for (int mt = 0; mt < 2; ++mt) {
            float p0 = psm[(wm * 32 + mt * 16 + lr) * 17 + leaf];
            float p1 = psm[(wm * 32 + mt * 16 + 8 + lr) * 17 + leaf];
            #pragma unroll
            for (int nt = 0; nt < 5; ++nt) {
                per[mt][nt][0] = fmaf(p0, acc[mt][nt][0], per[mt][nt][0]);
                per[mt][nt][1] = fmaf(p0, acc[mt][nt][1], per[mt][nt][1]);
                per[mt][nt][2] = fmaf(p1, acc[mt][nt][2], per[mt][nt][2]);
                per[mt][nt][3] = fmaf(p1, acc[mt][nt][3], per[mt][nt][3]);
            }
        }
    }

    float* base = g_partial + (size_t)grp * BB * CC;
    #pragma unroll
    for (int mt = 0; mt < 2; ++mt) {
        int r0 = rt * 128 + wm * 32 + mt * 16 + lr;
        #pragma unroll
        for (int nt = 0; nt < 5; ++nt) {
            int c0 = wn * 40 + nt * 8 + lc * 2;
            *(float2*)(base + (size_t)r0 * CC + c0) = make_float2(per[mt][nt][0], per[mt][nt][1]);
            *(float2*)(base + (size_t)(r0 + 8) * CC + c0) = make_float2(per[mt][nt][2], per[mt][nt][3]);
        }
    }
}

// ---------------- K6: reduce partials ----------------
__global__ void k_reduce(float* __restrict__ out) {
    int idx = blockIdx.x * 256 + threadIdx.x;
    float s = 0.f;
    #pragma unroll
    for (int g = 0; g < NGRP; ++g)
        s += g_partial[(size_t)g * BB * CC + idx];
    out[idx] = s;
}

// ---------------- launch (1 side stream; nsout overlaps k_main) ----------------
extern "C" void kernel_launch(void* const* d_in, const int* in_sizes, int n_in,
                              void* d_out, int out_size) {
    const float* x    = (const float*)d_in[0];
    const float* ne   = (const float*)d_in[1];
    const float* W    = (const float*)d_in[2];
    const float* bias = (const float*)d_in[3];

    float* out1 = (float*)d_out;
    float* ns   = (float*)d_out + BB * CC;

    cudaFuncSetAttribute(k_main, cudaFuncAttributeMaxDynamicSharedMemorySize, SMEM_MAIN);
    cudaFuncSetAttribute(k_nsim, cudaFuncAttributeMaxDynamicSharedMemorySize, SMEM_NS);

    cudaStream_t s2;
    cudaEvent_t eFork, eW, eZ, eOut;
    cudaStreamCreateWithFlags(&s2, cudaStreamNonBlocking);
    cudaEventCreateWithFlags(&eFork, cudaEventDisableTiming);
    cudaEventCreateWithFlags(&eW, cudaEventDisableTiming);
    cudaEventCreateWithFlags(&eZ, cudaEventDisableTiming);
    cudaEventCreateWithFlags(&eOut, cudaEventDisableTiming);

    cudaEventRecord(eFork, 0);
    cudaStreamWaitEvent(s2, eFork, 0);

    // s2: W conversion (gates k_main), then ns output (overlaps k_main)
    k_convW<<<5120, 256, 0, s2>>>(W);
    cudaEventRecord(eW, s2);

    // main: x conversion -> ne norm -> node-sim HMMA (z=4)
    k_convX<<<256, 256>>>(x);
    k_norm<<<KK, 128>>>(ne);
    dim3 gn(8, 4, 4);
    k_nsim<<<gn, 256, SMEM_NS>>>();
    cudaEventRecord(eZ, 0);

    cudaStreamWaitEvent(s2, eZ, 0);
    k_nsout<<<BB, 256, 0, s2>>>(ns);
    cudaEventRecord(eOut, s2);

    // main: big GEMM (waits for W; probs fused into its prologue) + reduce
    cudaStreamWaitEvent(0, eW, 0);
    dim3 g5(8, NGRP);
    k_main<<<g5, 256, SMEM_MAIN>>>(bias);
    k_reduce<<<(BB * CC) / 256, 256>>>(out1);
    cudaStreamWaitEvent(0, eOut, 0);

    // note: s2/events intentionally not destroyed — destroying capture-referenced
    // handles mid-capture is UB; bounded leak (1-stream pattern teardown-proven).
}